// round 1
// baseline (speedup 1.0000x reference)
#include <cuda_runtime.h>
#include <math_constants.h>

#define NFEAT 65536
#define FD    512
#define NC    256
#define RPC   (NFEAT / NC)      // 256 rows per class
#define F4D   (FD / 4)          // 128 float4 per row

// Scratch (no cudaMalloc allowed)
__device__ float g_centers[NC * FD];   // normalized centers
__device__ float g_rowval[NC];         // per-row (1 - min_off_diag)

// ---------------------------------------------------------------------------
// Kernel 1: per-class mean over 256 rows, fused L2 normalization.
// grid = 256 (one class per block), block = 128 threads (each owns one float4
// column group = 4 consecutive floats). Fully coalesced: 128 thr * 16B = 2KB/row.
// ---------------------------------------------------------------------------
__global__ void __launch_bounds__(128) centers_kernel(const float* __restrict__ feat) {
    const int c = blockIdx.x;
    const int t = threadIdx.x;                 // 0..127

    const float4* __restrict__ p =
        reinterpret_cast<const float4*>(feat) + (size_t)c * RPC * F4D + t;

    float4 acc = make_float4(0.f, 0.f, 0.f, 0.f);
    #pragma unroll 8
    for (int r = 0; r < RPC; ++r) {
        float4 v = p[(size_t)r * F4D];
        acc.x += v.x; acc.y += v.y; acc.z += v.z; acc.w += v.w;
    }
    const float inv = 1.0f / (float)RPC;
    acc.x *= inv; acc.y *= inv; acc.z *= inv; acc.w *= inv;

    // block-wide sum of squares (deterministic tree reduce)
    float ss = acc.x*acc.x + acc.y*acc.y + acc.z*acc.z + acc.w*acc.w;
    #pragma unroll
    for (int o = 16; o > 0; o >>= 1)
        ss += __shfl_xor_sync(0xffffffffu, ss, o);

    __shared__ float sred[4];
    if ((t & 31) == 0) sred[t >> 5] = ss;
    __syncthreads();
    float total = sred[0] + sred[1] + sred[2] + sred[3];

    float norm = sqrtf(total);
    float invn = 1.0f / fmaxf(norm, 1e-8f);

    float4 o4 = make_float4(acc.x * invn, acc.y * invn, acc.z * invn, acc.w * invn);
    reinterpret_cast<float4*>(g_centers)[(size_t)c * F4D + t] = o4;
}

// ---------------------------------------------------------------------------
// Kernel 2: cosine-sim row mins. 4 i-rows per block in shared; 8 warps each
// own j = warp, warp+8, ... Each warp dots c_j (global, L2-resident) against
// the 4 shared rows; full-warp shfl_xor reduce; off-diagonal min tracking.
// grid = NC/4 = 64, block = 256.
// ---------------------------------------------------------------------------
__global__ void __launch_bounds__(256) sim_kernel() {
    const int ib   = blockIdx.x * 4;           // rows [ib, ib+4)
    const int t    = threadIdx.x;
    const int w    = t >> 5;                   // warp 0..7
    const int lane = t & 31;

    __shared__ float sc[4 * FD];               // 8 KB
    {
        const float4* src = reinterpret_cast<const float4*>(g_centers + (size_t)ib * FD);
        float4* dst = reinterpret_cast<float4*>(sc);
        for (int k = t; k < 4 * F4D; k += 256) dst[k] = src[k];
    }
    __syncthreads();

    float mn0 = CUDART_INF_F, mn1 = CUDART_INF_F, mn2 = CUDART_INF_F, mn3 = CUDART_INF_F;

    const float4* s0 = reinterpret_cast<const float4*>(sc);
    const float4* s1 = s0 + F4D;
    const float4* s2 = s1 + F4D;
    const float4* s3 = s2 + F4D;

    for (int j = w; j < NC; j += 8) {
        const float4* cj = reinterpret_cast<const float4*>(g_centers + (size_t)j * FD);
        float d0 = 0.f, d1 = 0.f, d2 = 0.f, d3 = 0.f;
        #pragma unroll
        for (int k = 0; k < 4; ++k) {
            int idx = lane + k * 32;           // float4 index 0..127, coalesced
            float4 v  = cj[idx];
            float4 a0 = s0[idx], a1 = s1[idx], a2 = s2[idx], a3 = s3[idx];
            d0 += v.x*a0.x + v.y*a0.y + v.z*a0.z + v.w*a0.w;
            d1 += v.x*a1.x + v.y*a1.y + v.z*a1.z + v.w*a1.w;
            d2 += v.x*a2.x + v.y*a2.y + v.z*a2.z + v.w*a2.w;
            d3 += v.x*a3.x + v.y*a3.y + v.z*a3.z + v.w*a3.w;
        }
        #pragma unroll
        for (int o = 16; o > 0; o >>= 1) {
            d0 += __shfl_xor_sync(0xffffffffu, d0, o);
            d1 += __shfl_xor_sync(0xffffffffu, d1, o);
            d2 += __shfl_xor_sync(0xffffffffu, d2, o);
            d3 += __shfl_xor_sync(0xffffffffu, d3, o);
        }
        if (j != ib + 0) mn0 = fminf(mn0, d0);
        if (j != ib + 1) mn1 = fminf(mn1, d1);
        if (j != ib + 2) mn2 = fminf(mn2, d2);
        if (j != ib + 3) mn3 = fminf(mn3, d3);
    }

    __shared__ float smin[8][4];
    if (lane == 0) {
        smin[w][0] = mn0; smin[w][1] = mn1; smin[w][2] = mn2; smin[w][3] = mn3;
    }
    __syncthreads();
    if (t < 4) {
        float m = CUDART_INF_F;
        #pragma unroll
        for (int ww = 0; ww < 8; ++ww) m = fminf(m, smin[ww][t]);
        g_rowval[ib + t] = 1.0f - m;
    }
}

// ---------------------------------------------------------------------------
// Kernel 3: sum 256 per-row values -> scalar output. Single block.
// ---------------------------------------------------------------------------
__global__ void __launch_bounds__(256) sum_kernel(float* __restrict__ out) {
    const int t = threadIdx.x;
    float v = g_rowval[t];
    #pragma unroll
    for (int o = 16; o > 0; o >>= 1)
        v += __shfl_xor_sync(0xffffffffu, v, o);

    __shared__ float sred[8];
    if ((t & 31) == 0) sred[t >> 5] = v;
    __syncthreads();
    if (t == 0) {
        float total = 0.f;
        #pragma unroll
        for (int i = 0; i < 8; ++i) total += sred[i];
        out[0] = total;
    }
}

extern "C" void kernel_launch(void* const* d_in, const int* in_sizes, int n_in,
                              void* d_out, int out_size) {
    const float* feat = (const float*)d_in[0];
    // d_in[1] = label (int32) — labels are contiguous class blocks by
    // construction, matching the reference's chunk(n,0) semantics; unused.
    float* out = (float*)d_out;

    centers_kernel<<<NC, 128>>>(feat);
    sim_kernel<<<NC / 4, 256>>>();
    sum_kernel<<<1, 256>>>(out);
}

// round 2
// speedup vs baseline: 1.3599x; 1.3599x over previous
#include <cuda_runtime.h>
#include <math_constants.h>

#define NFEAT 65536
#define FD    512
#define NC    256
#define RPC   (NFEAT / NC)      // 256 rows per class
#define F4D   (FD / 4)          // 128 float4 per row
#define RSPLIT 4                // row-chunks per class
#define RCHUNK (RPC / RSPLIT)   // 64 rows per chunk

// Scratch (no cudaMalloc allowed)
__device__ float g_partial[RSPLIT * NC * FD];  // 2 MB partial sums
__device__ float g_centers[NC * FD];           // normalized centers
__device__ float g_rowval[NC];                 // per-row (1 - min_off_diag)

// ---------------------------------------------------------------------------
// Kernel 1a: partial sums. grid = NC*RSPLIT = 1024 blocks, 128 threads.
// Block b: class c = b >> 2, row chunk s = b & 3 (rows [s*64, s*64+64)).
// Each thread owns one float4 column group; fully coalesced 2KB/row reads.
// Streaming loads (__ldcs): feat has zero reuse, keep it out of L2.
// ---------------------------------------------------------------------------
__global__ void __launch_bounds__(128) centers_partial_kernel(const float* __restrict__ feat) {
    const int b = blockIdx.x;
    const int c = b >> 2;
    const int s = b & 3;
    const int t = threadIdx.x;                 // 0..127

    const float4* __restrict__ p =
        reinterpret_cast<const float4*>(feat)
        + ((size_t)c * RPC + (size_t)s * RCHUNK) * F4D + t;

    float4 acc = make_float4(0.f, 0.f, 0.f, 0.f);
    #pragma unroll 8
    for (int r = 0; r < RCHUNK; ++r) {
        float4 v = __ldcs(p + (size_t)r * F4D);
        acc.x += v.x; acc.y += v.y; acc.z += v.z; acc.w += v.w;
    }
    reinterpret_cast<float4*>(g_partial)[((size_t)s * NC + c) * F4D + t] = acc;
}

// ---------------------------------------------------------------------------
// Kernel 1b: fold RSPLIT partials, mean, fused L2 normalization.
// grid = 256 (one class per block), 128 threads.
// ---------------------------------------------------------------------------
__global__ void __launch_bounds__(128) centers_finalize_kernel() {
    const int c = blockIdx.x;
    const int t = threadIdx.x;

    float4 acc = make_float4(0.f, 0.f, 0.f, 0.f);
    #pragma unroll
    for (int s = 0; s < RSPLIT; ++s) {
        float4 v = reinterpret_cast<const float4*>(g_partial)[((size_t)s * NC + c) * F4D + t];
        acc.x += v.x; acc.y += v.y; acc.z += v.z; acc.w += v.w;
    }
    const float inv = 1.0f / (float)RPC;
    acc.x *= inv; acc.y *= inv; acc.z *= inv; acc.w *= inv;

    // block-wide sum of squares (deterministic tree reduce)
    float ss = acc.x*acc.x + acc.y*acc.y + acc.z*acc.z + acc.w*acc.w;
    #pragma unroll
    for (int o = 16; o > 0; o >>= 1)
        ss += __shfl_xor_sync(0xffffffffu, ss, o);

    __shared__ float sred[4];
    if ((t & 31) == 0) sred[t >> 5] = ss;
    __syncthreads();
    float total = sred[0] + sred[1] + sred[2] + sred[3];

    float norm = sqrtf(total);
    float invn = 1.0f / fmaxf(norm, 1e-8f);

    float4 o4 = make_float4(acc.x * invn, acc.y * invn, acc.z * invn, acc.w * invn);
    reinterpret_cast<float4*>(g_centers)[(size_t)c * F4D + t] = o4;
}

// ---------------------------------------------------------------------------
// Kernel 2: cosine-sim row mins. 4 i-rows per block in shared; 8 warps each
// own j = warp, warp+8, ... Warp dots c_j (L2-resident) against the 4 shared
// rows; shfl_xor reduce; off-diagonal min per i-row.
// grid = NC/4 = 64, block = 256.
// ---------------------------------------------------------------------------
__global__ void __launch_bounds__(256) sim_kernel() {
    const int ib   = blockIdx.x * 4;
    const int t    = threadIdx.x;
    const int w    = t >> 5;
    const int lane = t & 31;

    __shared__ float sc[4 * FD];               // 8 KB
    {
        const float4* src = reinterpret_cast<const float4*>(g_centers + (size_t)ib * FD);
        float4* dst = reinterpret_cast<float4*>(sc);
        for (int k = t; k < 4 * F4D; k += 256) dst[k] = src[k];
    }
    __syncthreads();

    float mn0 = CUDART_INF_F, mn1 = CUDART_INF_F, mn2 = CUDART_INF_F, mn3 = CUDART_INF_F;

    const float4* s0 = reinterpret_cast<const float4*>(sc);
    const float4* s1 = s0 + F4D;
    const float4* s2 = s1 + F4D;
    const float4* s3 = s2 + F4D;

    for (int j = w; j < NC; j += 8) {
        const float4* cj = reinterpret_cast<const float4*>(g_centers + (size_t)j * FD);
        float d0 = 0.f, d1 = 0.f, d2 = 0.f, d3 = 0.f;
        #pragma unroll
        for (int k = 0; k < 4; ++k) {
            int idx = lane + k * 32;
            float4 v  = cj[idx];
            float4 a0 = s0[idx], a1 = s1[idx], a2 = s2[idx], a3 = s3[idx];
            d0 += v.x*a0.x + v.y*a0.y + v.z*a0.z + v.w*a0.w;
            d1 += v.x*a1.x + v.y*a1.y + v.z*a1.z + v.w*a1.w;
            d2 += v.x*a2.x + v.y*a2.y + v.z*a2.z + v.w*a2.w;
            d3 += v.x*a3.x + v.y*a3.y + v.z*a3.z + v.w*a3.w;
        }
        #pragma unroll
        for (int o = 16; o > 0; o >>= 1) {
            d0 += __shfl_xor_sync(0xffffffffu, d0, o);
            d1 += __shfl_xor_sync(0xffffffffu, d1, o);
            d2 += __shfl_xor_sync(0xffffffffu, d2, o);
            d3 += __shfl_xor_sync(0xffffffffu, d3, o);
        }
        if (j != ib + 0) mn0 = fminf(mn0, d0);
        if (j != ib + 1) mn1 = fminf(mn1, d1);
        if (j != ib + 2) mn2 = fminf(mn2, d2);
        if (j != ib + 3) mn3 = fminf(mn3, d3);
    }

    __shared__ float smin[8][4];
    if (lane == 0) {
        smin[w][0] = mn0; smin[w][1] = mn1; smin[w][2] = mn2; smin[w][3] = mn3;
    }
    __syncthreads();
    if (t < 4) {
        float m = CUDART_INF_F;
        #pragma unroll
        for (int ww = 0; ww < 8; ++ww) m = fminf(m, smin[ww][t]);
        g_rowval[ib + t] = 1.0f - m;
    }
}

// ---------------------------------------------------------------------------
// Kernel 3: sum 256 per-row values -> scalar output. Single block.
// ---------------------------------------------------------------------------
__global__ void __launch_bounds__(256) sum_kernel(float* __restrict__ out) {
    const int t = threadIdx.x;
    float v = g_rowval[t];
    #pragma unroll
    for (int o = 16; o > 0; o >>= 1)
        v += __shfl_xor_sync(0xffffffffu, v, o);

    __shared__ float sred[8];
    if ((t & 31) == 0) sred[t >> 5] = v;
    __syncthreads();
    if (t == 0) {
        float total = 0.f;
        #pragma unroll
        for (int i = 0; i < 8; ++i) total += sred[i];
        out[0] = total;
    }
}

extern "C" void kernel_launch(void* const* d_in, const int* in_sizes, int n_in,
                              void* d_out, int out_size) {
    const float* feat = (const float*)d_in[0];
    float* out = (float*)d_out;

    centers_partial_kernel<<<NC * RSPLIT, 128>>>(feat);
    centers_finalize_kernel<<<NC, 128>>>();
    sim_kernel<<<NC / 4, 256>>>();
    sum_kernel<<<1, 256>>>(out);
}